// round 1
// baseline (speedup 1.0000x reference)
#include <cuda_runtime.h>
#include <math.h>

#define BSZ  256
#define HDIM 1024
#define DDIM 256
#define TLEN 64
#define FC1N 1024
#define FC2N 512

// ---------------- persistent state (allocation-free scratch) ----------------
__device__ float g_h0 [BSZ * HDIM];
__device__ float g_h1 [BSZ * HDIM];
__device__ float g_out[BSZ * DDIM];
__device__ float g_gi [BSZ * 3 * HDIM];
__device__ float g_gh [BSZ * 3 * HDIM];
__device__ float g_z1 [BSZ * FC1N];
__device__ float g_z2 [BSZ * FC2N];
__device__ float g_z3 [BSZ * DDIM];

// ---------------- init: h0 = hidden[0], h1 = hidden[1], out = 0 -------------
__global__ void init_kernel(const float* __restrict__ hidden) {
    int i = blockIdx.x * blockDim.x + threadIdx.x;
    if (i < BSZ * HDIM) {
        g_h0[i] = hidden[i];
        g_h1[i] = hidden[BSZ * HDIM + i];
    }
    if (i < BSZ * DDIM) g_out[i] = 0.0f;
}

// ---------------- generic GEMM: C[M,N] = A[M,K] @ W[N,K]^T + bias[N] --------
// BM=BN=64, BK=16, 256 threads, 4x4 microtile. M%64==0, N%64==0, K%16==0.
__global__ __launch_bounds__(256)
void gemm_nt(const float* __restrict__ A, const float* __restrict__ W,
             const float* __restrict__ bias, float* __restrict__ C,
             int M, int N, int K)
{
    __shared__ float sA[16][64];
    __shared__ float sB[16][64];

    const int tid = threadIdx.x;
    const int tx  = tid & 15;    // 0..15 -> n
    const int ty  = tid >> 4;    // 0..15 -> m
    const int row0 = blockIdx.y * 64;
    const int col0 = blockIdx.x * 64;

    const int lr = tid >> 2;          // 0..63 : tile row
    const int lq = (tid & 3) * 4;     // 0,4,8,12 : k quad

    float acc[4][4] = {};

    for (int kt = 0; kt < K; kt += 16) {
        float4 av = *(const float4*)(A + (size_t)(row0 + lr) * K + kt + lq);
        float4 wv = *(const float4*)(W + (size_t)(col0 + lr) * K + kt + lq);
        sA[lq + 0][lr] = av.x; sA[lq + 1][lr] = av.y;
        sA[lq + 2][lr] = av.z; sA[lq + 3][lr] = av.w;
        sB[lq + 0][lr] = wv.x; sB[lq + 1][lr] = wv.y;
        sB[lq + 2][lr] = wv.z; sB[lq + 3][lr] = wv.w;
        __syncthreads();

        #pragma unroll
        for (int kk = 0; kk < 16; kk++) {
            float4 a = *(const float4*)(&sA[kk][ty * 4]);
            float4 b = *(const float4*)(&sB[kk][tx * 4]);
            float ar[4] = {a.x, a.y, a.z, a.w};
            float br[4] = {b.x, b.y, b.z, b.w};
            #pragma unroll
            for (int i = 0; i < 4; i++)
                #pragma unroll
                for (int j = 0; j < 4; j++)
                    acc[i][j] = fmaf(ar[i], br[j], acc[i][j]);
        }
        __syncthreads();
    }

    #pragma unroll
    for (int i = 0; i < 4; i++) {
        int m = row0 + ty * 4 + i;
        #pragma unroll
        for (int j = 0; j < 4; j++) {
            int n = col0 + tx * 4 + j;
            C[(size_t)m * N + n] = acc[i][j] + bias[n];
        }
    }
}

// ---------------- GRU gates (in-place h update) -----------------------------
__device__ __forceinline__ float sigmoidf(float x) { return 1.0f / (1.0f + expf(-x)); }

__global__ void gru_gate(const float* __restrict__ gi, const float* __restrict__ gh,
                         float* __restrict__ h)
{
    int idx = blockIdx.x * blockDim.x + threadIdx.x;   // B*H threads
    int b = idx >> 10;          // /HDIM
    int j = idx & (HDIM - 1);
    const float* gib = gi + (size_t)b * 3 * HDIM;
    const float* ghb = gh + (size_t)b * 3 * HDIM;
    float r = sigmoidf(gib[j]            + ghb[j]);
    float z = sigmoidf(gib[HDIM + j]     + ghb[HDIM + j]);
    float n = tanhf   (gib[2 * HDIM + j] + r * ghb[2 * HDIM + j]);
    float hv = h[idx];
    h[idx] = (1.0f - z) * n + z * hv;
}

// ---------------- fused LayerNorm + exact GELU (in-place, per-row block) ----
template <int N>
__global__ void ln_gelu(float* __restrict__ x, const float* __restrict__ g,
                        const float* __restrict__ b)
{
    const int row = blockIdx.x;
    float* xr = x + (size_t)row * N;
    const int tid = threadIdx.x;

    float s = 0.0f, s2 = 0.0f;
    #pragma unroll
    for (int j = tid; j < N; j += 256) { float v = xr[j]; s += v; s2 += v * v; }

    __shared__ float rs[256], rs2[256];
    rs[tid] = s; rs2[tid] = s2;
    __syncthreads();
    #pragma unroll
    for (int o = 128; o > 0; o >>= 1) {
        if (tid < o) { rs[tid] += rs[tid + o]; rs2[tid] += rs2[tid + o]; }
        __syncthreads();
    }
    float mu  = rs[0]  * (1.0f / N);
    float var = rs2[0] * (1.0f / N) - mu * mu;
    float inv = rsqrtf(var + 1e-5f);

    #pragma unroll
    for (int j = tid; j < N; j += 256) {
        float v = (xr[j] - mu) * inv * g[j] + b[j];
        xr[j] = 0.5f * v * (1.0f + erff(v * 0.70710678118654752f));
    }
}

// ---------------- softmax + feedback + store to output ----------------------
__global__ void softmax_store(const float* __restrict__ z, float* __restrict__ out,
                              float* __restrict__ dst, int t)
{
    const int b = blockIdx.x;
    const int j = threadIdx.x;     // 256 == DDIM
    float v = z[(size_t)b * DDIM + j];

    __shared__ float red[256];
    red[j] = v;
    __syncthreads();
    #pragma unroll
    for (int o = 128; o > 0; o >>= 1) {
        if (j < o) red[j] = fmaxf(red[j], red[j + o]);
        __syncthreads();
    }
    float m = red[0];
    __syncthreads();
    float e = expf(v - m);
    red[j] = e;
    __syncthreads();
    #pragma unroll
    for (int o = 128; o > 0; o >>= 1) {
        if (j < o) red[j] += red[j + o];
        __syncthreads();
    }
    float p = e / red[0];
    out[(size_t)b * DDIM + j] = p;
    dst[((size_t)b * TLEN + t) * DDIM + j] = p;
}

// ---------------- host orchestration ----------------------------------------
static inline void launch_gemm(const float* A, const float* W, const float* bias,
                               float* C, int M, int N, int K)
{
    dim3 grid(N / 64, M / 64);
    gemm_nt<<<grid, 256>>>(A, W, bias, C, M, N, K);
}

extern "C" void kernel_launch(void* const* d_in, const int* in_sizes, int n_in,
                              void* d_out, int out_size)
{
    const float* hidden = (const float*)d_in[0];
    const float* W_ih0  = (const float*)d_in[1];
    const float* W_hh0  = (const float*)d_in[2];
    const float* b_ih0  = (const float*)d_in[3];
    const float* b_hh0  = (const float*)d_in[4];
    const float* W_ih1  = (const float*)d_in[5];
    const float* W_hh1  = (const float*)d_in[6];
    const float* b_ih1  = (const float*)d_in[7];
    const float* b_hh1  = (const float*)d_in[8];
    const float* fc1_w  = (const float*)d_in[9];
    const float* fc1_b  = (const float*)d_in[10];
    const float* ln1_g  = (const float*)d_in[11];
    const float* ln1_b  = (const float*)d_in[12];
    const float* fc2_w  = (const float*)d_in[13];
    const float* fc2_b  = (const float*)d_in[14];
    const float* ln2_g  = (const float*)d_in[15];
    const float* ln2_b  = (const float*)d_in[16];
    const float* fc3_w  = (const float*)d_in[17];
    const float* fc3_b  = (const float*)d_in[18];
    float* out = (float*)d_out;

    // resolve device-global scratch addresses (host-side, capture-time only)
    float *h0, *h1, *ob, *gi, *gh, *z1, *z2, *z3;
    cudaGetSymbolAddress((void**)&h0, g_h0);
    cudaGetSymbolAddress((void**)&h1, g_h1);
    cudaGetSymbolAddress((void**)&ob, g_out);
    cudaGetSymbolAddress((void**)&gi, g_gi);
    cudaGetSymbolAddress((void**)&gh, g_gh);
    cudaGetSymbolAddress((void**)&z1, g_z1);
    cudaGetSymbolAddress((void**)&z2, g_z2);
    cudaGetSymbolAddress((void**)&z3, g_z3);

    init_kernel<<<(BSZ * HDIM + 255) / 256, 256>>>(hidden);

    for (int t = 0; t < TLEN; t++) {
        // ---- GRU layer 0: input = out (D=256), state = h0 ----
        launch_gemm(ob, W_ih0, b_ih0, gi, BSZ, 3 * HDIM, DDIM);
        launch_gemm(h0, W_hh0, b_hh0, gh, BSZ, 3 * HDIM, HDIM);
        gru_gate<<<(BSZ * HDIM) / 256, 256>>>(gi, gh, h0);

        // ---- GRU layer 1: input = h0, state = h1 ----
        launch_gemm(h0, W_ih1, b_ih1, gi, BSZ, 3 * HDIM, HDIM);
        launch_gemm(h1, W_hh1, b_hh1, gh, BSZ, 3 * HDIM, HDIM);
        gru_gate<<<(BSZ * HDIM) / 256, 256>>>(gi, gh, h1);

        // ---- FC head ----
        launch_gemm(h1, fc1_w, fc1_b, z1, BSZ, FC1N, HDIM);
        ln_gelu<FC1N><<<BSZ, 256>>>(z1, ln1_g, ln1_b);
        launch_gemm(z1, fc2_w, fc2_b, z2, BSZ, FC2N, FC1N);
        ln_gelu<FC2N><<<BSZ, 256>>>(z2, ln2_g, ln2_b);
        launch_gemm(z2, fc3_w, fc3_b, z3, BSZ, DDIM, FC2N);

        // ---- softmax, feed back, store slice [:, t, :] ----
        softmax_store<<<BSZ, DDIM>>>(z3, ob, out, t);
    }
}

// round 3
// speedup vs baseline: 1.8179x; 1.8179x over previous
#include <cuda_runtime.h>
#include <cuda_bf16.h>
#include <math.h>
#include <stdint.h>

#define BSZ  256
#define HDIM 1024
#define DDIM 256
#define TLEN 64
#define FC1N 1024
#define FC2N 512

// ============================ PTX helpers ====================================
__device__ __forceinline__ uint32_t smem_u32(const void* p) {
    uint32_t a;
    asm("{ .reg .u64 t; cvta.to.shared.u64 t, %1; cvt.u32.u64 %0, t; }" : "=r"(a) : "l"(p));
    return a;
}
__device__ __forceinline__ void ldmx4(uint32_t* r, uint32_t addr) {
    asm volatile("ldmatrix.sync.aligned.m8n8.x4.shared.b16 {%0,%1,%2,%3}, [%4];"
        : "=r"(r[0]), "=r"(r[1]), "=r"(r[2]), "=r"(r[3]) : "r"(addr));
}
__device__ __forceinline__ void mma_bf16(float* d, const uint32_t* a, const uint32_t* b) {
    asm volatile("mma.sync.aligned.m16n8k16.row.col.f32.bf16.bf16.f32 "
        "{%0,%1,%2,%3}, {%4,%5,%6,%7}, {%8,%9}, {%0,%1,%2,%3};"
        : "+f"(d[0]), "+f"(d[1]), "+f"(d[2]), "+f"(d[3])
        : "r"(a[0]), "r"(a[1]), "r"(a[2]), "r"(a[3]), "r"(b[0]), "r"(b[1]));
}
__device__ __forceinline__ void cpasync16(uint32_t dst, const void* src) {
    asm volatile("cp.async.cg.shared.global [%0], [%1], 16;" :: "r"(dst), "l"(src));
}
#define CP_COMMIT asm volatile("cp.async.commit_group;" ::: "memory")
#define CP_WAIT0  asm volatile("cp.async.wait_group 0;" ::: "memory")

// ====================== persistent device scratch ============================
__device__ float g_h0f[BSZ * HDIM];
__device__ float g_h1f[BSZ * HDIM];
__device__ float g_gi [BSZ * 3 * HDIM];
__device__ float g_gh [BSZ * 3 * HDIM];
__device__ float g_z1f[BSZ * FC1N];
__device__ float g_z2f[BSZ * FC2N];
__device__ float g_z3 [BSZ * DDIM];
__device__ __nv_bfloat16 g_out_hi[BSZ * DDIM],  g_out_lo[BSZ * DDIM];
__device__ __nv_bfloat16 g_h0_hi [BSZ * HDIM],  g_h0_lo [BSZ * HDIM];
__device__ __nv_bfloat16 g_h1_hi [BSZ * HDIM],  g_h1_lo [BSZ * HDIM];
__device__ __nv_bfloat16 g_z1_hi [BSZ * FC1N],  g_z1_lo [BSZ * FC1N];
__device__ __nv_bfloat16 g_z2_hi [BSZ * FC2N],  g_z2_lo [BSZ * FC2N];
__device__ __nv_bfloat16 g_wih0_hi[3*HDIM*DDIM], g_wih0_lo[3*HDIM*DDIM];
__device__ __nv_bfloat16 g_whh0_hi[3*HDIM*HDIM], g_whh0_lo[3*HDIM*HDIM];
__device__ __nv_bfloat16 g_wih1_hi[3*HDIM*HDIM], g_wih1_lo[3*HDIM*HDIM];
__device__ __nv_bfloat16 g_whh1_hi[3*HDIM*HDIM], g_whh1_lo[3*HDIM*HDIM];
__device__ __nv_bfloat16 g_fc1_hi[FC1N*HDIM],    g_fc1_lo[FC1N*HDIM];
__device__ __nv_bfloat16 g_fc2_hi[FC2N*FC1N],    g_fc2_lo[FC2N*FC1N];
__device__ __nv_bfloat16 g_fc3_hi[DDIM*FC2N],    g_fc3_lo[DDIM*FC2N];

// ============================ small kernels ==================================
__global__ void split_kernel(const float* __restrict__ x,
                             __nv_bfloat16* __restrict__ hi,
                             __nv_bfloat16* __restrict__ lo, int n) {
    int i = blockIdx.x * blockDim.x + threadIdx.x;
    if (i < n) {
        float v = x[i];
        __nv_bfloat16 h = __float2bfloat16(v);
        hi[i] = h;
        lo[i] = __float2bfloat16(v - __bfloat162float(h));
    }
}

__global__ void init_kernel(const float* __restrict__ hidden) {
    int i = blockIdx.x * blockDim.x + threadIdx.x;
    if (i < BSZ * HDIM) {
        float v0 = hidden[i];
        float v1 = hidden[BSZ * HDIM + i];
        g_h0f[i] = v0; g_h1f[i] = v1;
        __nv_bfloat16 h0 = __float2bfloat16(v0);
        __nv_bfloat16 h1 = __float2bfloat16(v1);
        g_h0_hi[i] = h0; g_h0_lo[i] = __float2bfloat16(v0 - __bfloat162float(h0));
        g_h1_hi[i] = h1; g_h1_lo[i] = __float2bfloat16(v1 - __bfloat162float(h1));
    }
    if (i < BSZ * DDIM) {
        g_out_hi[i] = __float2bfloat16(0.0f);
        g_out_lo[i] = __float2bfloat16(0.0f);
    }
}

__device__ __forceinline__ float sigmoidf_(float x) { return 1.0f / (1.0f + expf(-x)); }

__global__ void gru_gate(const float4* __restrict__ gi, const float4* __restrict__ gh,
                         float4* __restrict__ h,
                         __nv_bfloat16* __restrict__ hhi, __nv_bfloat16* __restrict__ hlo)
{
    int idx = blockIdx.x * blockDim.x + threadIdx.x;   // B*H/4 threads
    int b = idx >> 8;
    int j = idx & 255;
    const float4* gib = gi + (size_t)b * 768;
    const float4* ghb = gh + (size_t)b * 768;
    float4 ir = gib[j],        iz = gib[256 + j], in4 = gib[512 + j];
    float4 hr = ghb[j],        hz = ghb[256 + j], hn4 = ghb[512 + j];
    float4 hv = h[idx];
    float out[4];
    float irA[4] = {ir.x, ir.y, ir.z, ir.w}, izA[4] = {iz.x, iz.y, iz.z, iz.w};
    float inA[4] = {in4.x, in4.y, in4.z, in4.w};
    float hrA[4] = {hr.x, hr.y, hr.z, hr.w}, hzA[4] = {hz.x, hz.y, hz.z, hz.w};
    float hnA[4] = {hn4.x, hn4.y, hn4.z, hn4.w};
    float hvA[4] = {hv.x, hv.y, hv.z, hv.w};
    #pragma unroll
    for (int k = 0; k < 4; k++) {
        float r = sigmoidf_(irA[k] + hrA[k]);
        float z = sigmoidf_(izA[k] + hzA[k]);
        float n = tanhf(inA[k] + r * hnA[k]);
        out[k] = (1.0f - z) * n + z * hvA[k];
    }
    h[idx] = make_float4(out[0], out[1], out[2], out[3]);
    int base = idx * 4;
    #pragma unroll
    for (int k = 0; k < 4; k++) {
        __nv_bfloat16 hb = __float2bfloat16(out[k]);
        hhi[base + k] = hb;
        hlo[base + k] = __float2bfloat16(out[k] - __bfloat162float(hb));
    }
}

template <int N>
__global__ void ln_gelu(const float* __restrict__ x, const float* __restrict__ g,
                        const float* __restrict__ b,
                        __nv_bfloat16* __restrict__ hi, __nv_bfloat16* __restrict__ lo)
{
    const int row = blockIdx.x;
    const float* xr = x + (size_t)row * N;
    const int tid = threadIdx.x;

    float s = 0.0f, s2 = 0.0f;
    #pragma unroll
    for (int j = tid; j < N; j += 256) { float v = xr[j]; s += v; s2 += v * v; }

    __shared__ float rs[256], rs2[256];
    rs[tid] = s; rs2[tid] = s2;
    __syncthreads();
    #pragma unroll
    for (int o = 128; o > 0; o >>= 1) {
        if (tid < o) { rs[tid] += rs[tid + o]; rs2[tid] += rs2[tid + o]; }
        __syncthreads();
    }
    float mu  = rs[0]  * (1.0f / N);
    float var = rs2[0] * (1.0f / N) - mu * mu;
    float inv = rsqrtf(var + 1e-5f);

    #pragma unroll
    for (int j = tid; j < N; j += 256) {
        float v = (xr[j] - mu) * inv * g[j] + b[j];
        float gv = 0.5f * v * (1.0f + erff(v * 0.70710678118654752f));
        __nv_bfloat16 hb = __float2bfloat16(gv);
        hi[(size_t)row * N + j] = hb;
        lo[(size_t)row * N + j] = __float2bfloat16(gv - __bfloat162float(hb));
    }
}

__global__ void softmax_store(const float* __restrict__ z,
                              __nv_bfloat16* __restrict__ ohi, __nv_bfloat16* __restrict__ olo,
                              float* __restrict__ dst, int t)
{
    const int b = blockIdx.x;
    const int j = threadIdx.x;     // 256 == DDIM
    float v = z[(size_t)b * DDIM + j];

    __shared__ float red[256];
    red[j] = v;
    __syncthreads();
    #pragma unroll
    for (int o = 128; o > 0; o >>= 1) {
        if (j < o) red[j] = fmaxf(red[j], red[j + o]);
        __syncthreads();
    }
    float m = red[0];
    __syncthreads();
    float e = expf(v - m);
    red[j] = e;
    __syncthreads();
    #pragma unroll
    for (int o = 128; o > 0; o >>= 1) {
        if (j < o) red[j] += red[j + o];
        __syncthreads();
    }
    float p = e / red[0];
    __nv_bfloat16 hb = __float2bfloat16(p);
    ohi[(size_t)b * DDIM + j] = hb;
    olo[(size_t)b * DDIM + j] = __float2bfloat16(p - __bfloat162float(hb));
    dst[((size_t)b * TLEN + t) * DDIM + j] = p;
}

// ===================== mma.sync split-bf16 GEMM ==============================
// C[M,N] = (Ahi+Alo)[M,K] @ (Bhi+Blo)[N,K]^T + bias   (lo*lo dropped)
// BK = 32. smem rows padded to 40 bf16 (80B pitch) -> conflict-free ldmatrix.
template <int BM, int BN, int WM, int WN>
__global__ __launch_bounds__(256)
void gemm_mma(const __nv_bfloat16* __restrict__ Ahi, const __nv_bfloat16* __restrict__ Alo,
              const __nv_bfloat16* __restrict__ Bhi, const __nv_bfloat16* __restrict__ Blo,
              const float* __restrict__ bias, float* __restrict__ C,
              int N, int K)
{
    constexpr int PITCH = 80;                 // bytes per 32-elem row (+16B pad)
    constexpr int A_SZ  = BM * PITCH;
    constexpr int B_SZ  = BN * PITCH;
    constexpr int STAGE = 2 * A_SZ + 2 * B_SZ;
    constexpr int WARPS_N = BN / WN;
    constexpr int MT  = WM / 16;
    constexpr int NT  = WN / 8;
    constexpr int NT2 = WN / 16;

    extern __shared__ char smem[];
    const uint32_t sb = smem_u32(smem);
    const int tid  = threadIdx.x;
    const int wid  = tid >> 5;
    const int lane = tid & 31;
    const int wm0 = (wid / WARPS_N) * WM;
    const int wn0 = (wid % WARPS_N) * WN;
    const int row0 = blockIdx.y * BM;
    const int col0 = blockIdx.x * BN;
    const int NC = K >> 5;

    float acc[MT][NT][4] = {};

    auto copy_chunk = [&](int c, int buf) {
        const uint32_t base = sb + buf * STAGE;
        const int kb = c << 5;
        #pragma unroll
        for (int i = tid; i < BM * 4; i += 256) {
            int r = i >> 2, q = i & 3;
            size_t g = (size_t)(row0 + r) * K + kb + q * 8;
            uint32_t d = base + r * PITCH + q * 16;
            cpasync16(d,        Ahi + g);
            cpasync16(d + A_SZ, Alo + g);
        }
        #pragma unroll
        for (int i = tid; i < BN * 4; i += 256) {
            int r = i >> 2, q = i & 3;
            size_t g = (size_t)(col0 + r) * K + kb + q * 8;
            uint32_t d = base + 2 * A_SZ + r * PITCH + q * 16;
            cpasync16(d,        Bhi + g);
            cpasync16(d + B_SZ, Blo + g);
        }
    };

    copy_chunk(0, 0);
    CP_COMMIT;

    int buf = 0;
    for (int c = 0; c < NC; c++) {
        CP_WAIT0;
        __syncthreads();
        if (c + 1 < NC) { copy_chunk(c + 1, buf ^ 1); CP_COMMIT; }

        const uint32_t aBase = sb + buf * STAGE;
        const uint32_t bBase = aBase + 2 * A_SZ;

        #pragma unroll
        for (int ks = 0; ks < 2; ks++) {
            uint32_t ah[MT][4], al[MT][4], bh[NT2][4], bl[NT2][4];
            #pragma unroll
            for (int mt = 0; mt < MT; mt++) {
                uint32_t ad = aBase + (wm0 + mt * 16 + (lane & 15)) * PITCH
                            + ks * 32 + ((lane >> 4) << 4);
                ldmx4(ah[mt], ad);
                ldmx4(al[mt], ad + A_SZ);
            }
            #pragma unroll
            for (int n2 = 0; n2 < NT2; n2++) {
                int nr = wn0 + n2 * 16 + (lane & 7) + ((lane & 16) ? 8 : 0);
                uint32_t bd = bBase + nr * PITCH + ks * 32 + ((lane & 8) ? 16 : 0);
                ldmx4(bh[n2], bd);
                ldmx4(bl[n2], bd + B_SZ);
            }
            #pragma unroll
            for (int mt = 0; mt < MT; mt++)
                #pragma unroll
                for (int nt = 0; nt < NT; nt++) {
                    const uint32_t* bph = &bh[nt >> 1][(nt & 1) * 2];
                    const uint32_t* bpl = &bl[nt >> 1][(nt & 1) * 2];
                    mma_bf16(acc[mt][nt], ah[mt], bph);
                    mma_bf16(acc[mt][nt], ah[mt], bpl);
                    mma_bf16(acc[mt][nt], al[mt], bph);
                }
        }
        __syncthreads();
        buf ^= 1;
    }

    // epilogue: C += bias
    #pragma unroll
    for (int mt = 0; mt < MT; mt++) {
        int r0 = row0 + wm0 + mt * 16 + (lane >> 2);
        #pragma unroll
        for (int nt = 0; nt < NT; nt++) {
            int cc = col0 + wn0 + nt * 8 + (lane & 3) * 2;
            float2 b2 = *(const float2*)(bias + cc);
            float2 v0 = { acc[mt][nt][0] + b2.x, acc[mt][nt][1] + b2.y };
            float2 v1 = { acc[mt][nt][2] + b2.x, acc[mt][nt][3] + b2.y };
            *(float2*)(C + (size_t)r0 * N + cc)       = v0;
            *(float2*)(C + (size_t)(r0 + 8) * N + cc) = v1;
        }
    }
}

// ============================ host side ======================================
#define SMEM_BIG   (2 * (2 * 128 * 80 + 2 * 64 * 80))   // 61440
#define SMEM_SMALL (2 * (2 * 64 * 80 + 2 * 64 * 80))    // 40960

static inline void gemm_big(const __nv_bfloat16* Ahi, const __nv_bfloat16* Alo,
                            const __nv_bfloat16* Bhi, const __nv_bfloat16* Blo,
                            const float* bias, float* C, int N, int K)
{
    dim3 grid(N / 64, BSZ / 128);
    gemm_mma<128, 64, 32, 32><<<grid, 256, SMEM_BIG>>>(Ahi, Alo, Bhi, Blo, bias, C, N, K);
}
static inline void gemm_small(const __nv_bfloat16* Ahi, const __nv_bfloat16* Alo,
                              const __nv_bfloat16* Bhi, const __nv_bfloat16* Blo,
                              const float* bias, float* C, int N, int K)
{
    dim3 grid(N / 64, BSZ / 64);
    gemm_mma<64, 64, 32, 16><<<grid, 256, SMEM_SMALL>>>(Ahi, Alo, Bhi, Blo, bias, C, N, K);
}

extern "C" void kernel_launch(void* const* d_in, const int* in_sizes, int n_in,
                              void* d_out, int out_size)
{
    const float* hidden = (const float*)d_in[0];
    const float* W_ih0  = (const float*)d_in[1];
    const float* W_hh0  = (const float*)d_in[2];
    const float* b_ih0  = (const float*)d_in[3];
    const float* b_hh0  = (const float*)d_in[4];
    const float* W_ih1  = (const float*)d_in[5];
    const float* W_hh1  = (const float*)d_in[6];
    const float* b_ih1  = (const float*)d_in[7];
    const float* b_hh1  = (const float*)d_in[8];
    const float* fc1_w  = (const float*)d_in[9];
    const float* fc1_b  = (const float*)d_in[10];
    const float* ln1_g  = (const float*)d_in[11];
    const float* ln1_b  = (const float*)d_in[12];
    const float* fc2_w  = (const float*)d_in[13];
    const float* fc2_b  = (const float*)d_in[14];
    const float* ln2_g  = (const float*)d_in[15];
    const float* ln2_b  = (const float*)d_in[16];
    const float* fc3_w  = (const float*)d_in[17];
    const float* fc3_b  = (const float*)d_in[18];
    float* out = (float*)d_out;

    cudaFuncSetAttribute((const void*)gemm_mma<128, 64, 32, 32>,
                         cudaFuncAttributeMaxDynamicSharedMemorySize, SMEM_BIG);
    cudaFuncSetAttribute((const void*)gemm_mma<64, 64, 32, 16>,
                         cudaFuncAttributeMaxDynamicSharedMemorySize, SMEM_SMALL);

    float *h0f, *h1f, *gi, *gh, *z1f, *z2f, *z3;
    __nv_bfloat16 *ohi, *olo, *h0hi, *h0lo, *h1hi, *h1lo, *z1hi, *z1lo, *z2hi, *z2lo;
    __nv_bfloat16 *wih0h, *wih0l, *whh0h, *whh0l, *wih1h, *wih1l, *whh1h, *whh1l;
    __nv_bfloat16 *f1h, *f1l, *f2h, *f2l, *f3h, *f3l;
    cudaGetSymbolAddress((void**)&h0f, g_h0f);  cudaGetSymbolAddress((void**)&h1f, g_h1f);
    cudaGetSymbolAddress((void**)&gi,  g_gi);   cudaGetSymbolAddress((void**)&gh,  g_gh);
    cudaGetSymbolAddress((void**)&z1f, g_z1f);  cudaGetSymbolAddress((void**)&z2f, g_z2f);
    cudaGetSymbolAddress((void**)&z3,  g_z3);
    cudaGetSymbolAddress((void**)&ohi, g_out_hi); cudaGetSymbolAddress((void**)&olo, g_out_lo);
    cudaGetSymbolAddress((void**)&h0hi, g_h0_hi); cudaGetSymbolAddress((void**)&h0lo, g_h0_lo);
    cudaGetSymbolAddress((void**)&h1hi, g_h1_hi); cudaGetSymbolAddress((void**)&h1lo, g_h1_lo);
    cudaGetSymbolAddress((void**)&z1hi, g_z1_hi); cudaGetSymbolAddress((void**)&z1lo, g_z1_lo);
    cudaGetSymbolAddress((void**)&z2hi, g_z2_hi); cudaGetSymbolAddress((void**)&z2lo, g_z2_lo);
    cudaGetSymbolAddress((void**)&wih0h, g_wih0_hi); cudaGetSymbolAddress((void**)&wih0l, g_wih0_lo);
    cudaGetSymbolAddress((void**)&whh0h, g_whh0_hi); cudaGetSymbolAddress((void**)&whh0l, g_whh0_lo);
    cudaGetSymbolAddress((void**)&wih1h, g_wih1_hi); cudaGetSymbolAddress((void**)&wih1l, g_wih1_lo);
    cudaGetSymbolAddress((void**)&whh1h, g_whh1_hi); cudaGetSymbolAddress((void**)&whh1l, g_whh1_lo);
    cudaGetSymbolAddress((void**)&f1h, g_fc1_hi); cudaGetSymbolAddress((void**)&f1l, g_fc1_lo);
    cudaGetSymbolAddress((void**)&f2h, g_fc2_hi); cudaGetSymbolAddress((void**)&f2l, g_fc2_lo);
    cudaGetSymbolAddress((void**)&f3h, g_fc3_hi); cudaGetSymbolAddress((void**)&f3l, g_fc3_lo);

    auto split = [](const float* src, __nv_bfloat16* hi, __nv_bfloat16* lo, int n) {
        split_kernel<<<n / 256, 256>>>(src, hi, lo, n);
    };
    split(W_ih0, wih0h, wih0l, 3 * HDIM * DDIM);
    split(W_hh0, whh0h, whh0l, 3 * HDIM * HDIM);
    split(W_ih1, wih1h, wih1l, 3 * HDIM * HDIM);
    split(W_hh1, whh1h, whh1l, 3 * HDIM * HDIM);
    split(fc1_w, f1h, f1l, FC1N * HDIM);
    split(fc2_w, f2h, f2l, FC2N * FC1N);
    split(fc3_w, f3h, f3l, DDIM * FC2N);

    init_kernel<<<(BSZ * HDIM + 255) / 256, 256>>>(hidden);

    for (int t = 0; t < TLEN; t++) {
        // ---- GRU layer 0 ----
        gemm_big(ohi, olo, wih0h, wih0l, b_ih0, gi, 3 * HDIM, DDIM);
        gemm_big(h0hi, h0lo, whh0h, whh0l, b_hh0, gh, 3 * HDIM, HDIM);
        gru_gate<<<(BSZ * HDIM / 4) / 256, 256>>>((const float4*)gi, (const float4*)gh,
                                                  (float4*)h0f, h0hi, h0lo);
        // ---- GRU layer 1 ----
        gemm_big(h0hi, h0lo, wih1h, wih1l, b_ih1, gi, 3 * HDIM, HDIM);
        gemm_big(h1hi, h1lo, whh1h, whh1l, b_hh1, gh, 3 * HDIM, HDIM);
        gru_gate<<<(BSZ * HDIM / 4) / 256, 256>>>((const float4*)gi, (const float4*)gh,
                                                  (float4*)h1f, h1hi, h1lo);
        // ---- FC head ----
        gemm_small(h1hi, h1lo, f1h, f1l, fc1_b, z1f, FC1N, HDIM);
        ln_gelu<FC1N><<<BSZ, 256>>>(z1f, ln1_g, ln1_b, z1hi, z1lo);
        gemm_small(z1hi, z1lo, f2h, f2l, fc2_b, z2f, FC2N, FC1N);
        ln_gelu<FC2N><<<BSZ, 256>>>(z2f, ln2_g, ln2_b, z2hi, z2lo);
        gemm_small(z2hi, z2lo, f3h, f3l, fc3_b, z3, DDIM, FC2N);
        // ---- softmax + feedback + store ----
        softmax_store<<<BSZ, DDIM>>>(z3, ohi, olo, out, t);
    }
}

// round 7
// speedup vs baseline: 3.8616x; 2.1242x over previous
#include <cuda_runtime.h>
#include <cuda_bf16.h>
#include <math.h>
#include <stdint.h>

#define BSZ  256
#define HDIM 1024
#define DDIM 256
#define TLEN 64
#define FC1N 1024
#define FC2N 512

// ============================ PTX helpers ====================================
__device__ __forceinline__ uint32_t smem_u32(const void* p) {
    uint32_t a;
    asm("{ .reg .u64 t; cvta.to.shared.u64 t, %1; cvt.u32.u64 %0, t; }" : "=r"(a) : "l"(p));
    return a;
}
__device__ __forceinline__ void ldmx4(uint32_t* r, uint32_t addr) {
    asm volatile("ldmatrix.sync.aligned.m8n8.x4.shared.b16 {%0,%1,%2,%3}, [%4];"
        : "=r"(r[0]), "=r"(r[1]), "=r"(r[2]), "=r"(r[3]) : "r"(addr));
}
__device__ __forceinline__ void mma_bf16(float* d, const uint32_t* a, const uint32_t* b) {
    asm volatile("mma.sync.aligned.m16n8k16.row.col.f32.bf16.bf16.f32 "
        "{%0,%1,%2,%3}, {%4,%5,%6,%7}, {%8,%9}, {%0,%1,%2,%3};"
        : "+f"(d[0]), "+f"(d[1]), "+f"(d[2]), "+f"(d[3])
        : "r"(a[0]), "r"(a[1]), "r"(a[2]), "r"(a[3]), "r"(b[0]), "r"(b[1]));
}
__device__ __forceinline__ void cpasync16(uint32_t dst, const void* src) {
    asm volatile("cp.async.cg.shared.global [%0], [%1], 16;" :: "r"(dst), "l"(src));
}
#define CP_COMMIT asm volatile("cp.async.commit_group;" ::: "memory")
#define CP_WAIT0  asm volatile("cp.async.wait_group 0;" ::: "memory")

// ====================== persistent device scratch ============================
__device__ float g_h0f[BSZ * HDIM];
__device__ float g_h1f[BSZ * HDIM];
__device__ float g_giA[BSZ * 3 * HDIM], g_giB[BSZ * 3 * HDIM];
__device__ float g_ghA[BSZ * 3 * HDIM], g_ghB[BSZ * 3 * HDIM];
__device__ float g_z1A[BSZ * FC1N], g_z1B[BSZ * FC1N];
__device__ float g_z2A[BSZ * FC2N], g_z2B[BSZ * FC2N];
__device__ float g_z3A[BSZ * DDIM], g_z3B[BSZ * DDIM];
__device__ __nv_bfloat16 g_out_hi[BSZ * DDIM],  g_out_lo[BSZ * DDIM];
__device__ __nv_bfloat16 g_h0_hi [BSZ * HDIM],  g_h0_lo [BSZ * HDIM];
__device__ __nv_bfloat16 g_h1_hi [BSZ * HDIM],  g_h1_lo [BSZ * HDIM];
__device__ __nv_bfloat16 g_z1_hi [BSZ * FC1N],  g_z1_lo [BSZ * FC1N];
__device__ __nv_bfloat16 g_z2_hi [BSZ * FC2N],  g_z2_lo [BSZ * FC2N];
__device__ __nv_bfloat16 g_wih0_hi[3*HDIM*DDIM], g_wih0_lo[3*HDIM*DDIM];
__device__ __nv_bfloat16 g_whh0_hi[3*HDIM*HDIM], g_whh0_lo[3*HDIM*HDIM];
__device__ __nv_bfloat16 g_wih1_hi[3*HDIM*HDIM], g_wih1_lo[3*HDIM*HDIM];
__device__ __nv_bfloat16 g_whh1_hi[3*HDIM*HDIM], g_whh1_lo[3*HDIM*HDIM];
__device__ __nv_bfloat16 g_fc1_hi[FC1N*HDIM],    g_fc1_lo[FC1N*HDIM];
__device__ __nv_bfloat16 g_fc2_hi[FC2N*FC1N],    g_fc2_lo[FC2N*FC1N];
__device__ __nv_bfloat16 g_fc3_hi[DDIM*FC2N],    g_fc3_lo[DDIM*FC2N];

// ============================ small kernels ==================================
__global__ void split_kernel(const float* __restrict__ x,
                             __nv_bfloat16* __restrict__ hi,
                             __nv_bfloat16* __restrict__ lo, int n) {
    int i = blockIdx.x * blockDim.x + threadIdx.x;
    if (i < n) {
        float v = x[i];
        __nv_bfloat16 h = __float2bfloat16(v);
        hi[i] = h;
        lo[i] = __float2bfloat16(v - __bfloat162float(h));
    }
}

__global__ void init_kernel(const float* __restrict__ hidden) {
    int i = blockIdx.x * blockDim.x + threadIdx.x;
    if (i < BSZ * HDIM) {
        float v0 = hidden[i];
        float v1 = hidden[BSZ * HDIM + i];
        g_h0f[i] = v0; g_h1f[i] = v1;
        __nv_bfloat16 h0 = __float2bfloat16(v0);
        __nv_bfloat16 h1 = __float2bfloat16(v1);
        g_h0_hi[i] = h0; g_h0_lo[i] = __float2bfloat16(v0 - __bfloat162float(h0));
        g_h1_hi[i] = h1; g_h1_lo[i] = __float2bfloat16(v1 - __bfloat162float(h1));
    }
    if (i < BSZ * DDIM) {
        g_out_hi[i] = __float2bfloat16(0.0f);
        g_out_lo[i] = __float2bfloat16(0.0f);
    }
}

__device__ __forceinline__ float sigmoidf_(float x) { return 1.0f / (1.0f + expf(-x)); }

// gate: gi = giA + giB + b_ih ; gh = ghA + ghB + b_hh
__global__ void gru_gate(const float4* __restrict__ giA, const float4* __restrict__ giB,
                         const float4* __restrict__ ghA, const float4* __restrict__ ghB,
                         const float4* __restrict__ bih, const float4* __restrict__ bhh,
                         float4* __restrict__ h,
                         __nv_bfloat16* __restrict__ hhi, __nv_bfloat16* __restrict__ hlo)
{
    int idx = blockIdx.x * blockDim.x + threadIdx.x;   // B*H/4 threads
    int b = idx >> 8;
    int j = idx & 255;
    size_t o = (size_t)b * 768;
    float4 ir4, iz4, in4, hr4, hz4, hn4;
    {
        float4 a, c, bb;
        a = giA[o + j];       c = giB[o + j];       bb = bih[j];
        ir4 = make_float4(a.x + c.x + bb.x, a.y + c.y + bb.y, a.z + c.z + bb.z, a.w + c.w + bb.w);
        a = giA[o + 256 + j]; c = giB[o + 256 + j]; bb = bih[256 + j];
        iz4 = make_float4(a.x + c.x + bb.x, a.y + c.y + bb.y, a.z + c.z + bb.z, a.w + c.w + bb.w);
        a = giA[o + 512 + j]; c = giB[o + 512 + j]; bb = bih[512 + j];
        in4 = make_float4(a.x + c.x + bb.x, a.y + c.y + bb.y, a.z + c.z + bb.z, a.w + c.w + bb.w);
        a = ghA[o + j];       c = ghB[o + j];       bb = bhh[j];
        hr4 = make_float4(a.x + c.x + bb.x, a.y + c.y + bb.y, a.z + c.z + bb.z, a.w + c.w + bb.w);
        a = ghA[o + 256 + j]; c = ghB[o + 256 + j]; bb = bhh[256 + j];
        hz4 = make_float4(a.x + c.x + bb.x, a.y + c.y + bb.y, a.z + c.z + bb.z, a.w + c.w + bb.w);
        a = ghA[o + 512 + j]; c = ghB[o + 512 + j]; bb = bhh[512 + j];
        hn4 = make_float4(a.x + c.x + bb.x, a.y + c.y + bb.y, a.z + c.z + bb.z, a.w + c.w + bb.w);
    }
    float4 hv = h[idx];
    float irA[4] = {ir4.x, ir4.y, ir4.z, ir4.w}, izA[4] = {iz4.x, iz4.y, iz4.z, iz4.w};
    float inA[4] = {in4.x, in4.y, in4.z, in4.w};
    float hrA[4] = {hr4.x, hr4.y, hr4.z, hr4.w}, hzA[4] = {hz4.x, hz4.y, hz4.z, hz4.w};
    float hnA[4] = {hn4.x, hn4.y, hn4.z, hn4.w};
    float hvA[4] = {hv.x, hv.y, hv.z, hv.w};
    float out[4];
    #pragma unroll
    for (int k = 0; k < 4; k++) {
        float r = sigmoidf_(irA[k] + hrA[k]);
        float z = sigmoidf_(izA[k] + hzA[k]);
        float n = tanhf(inA[k] + r * hnA[k]);
        out[k] = (1.0f - z) * n + z * hvA[k];
    }
    h[idx] = make_float4(out[0], out[1], out[2], out[3]);
    int base = idx * 4;
    #pragma unroll
    for (int k = 0; k < 4; k++) {
        __nv_bfloat16 hb = __float2bfloat16(out[k]);
        hhi[base + k] = hb;
        hlo[base + k] = __float2bfloat16(out[k] - __bfloat162float(hb));
    }
}

template <int N>
__global__ void ln_gelu(const float* __restrict__ xa, const float* __restrict__ xb,
                        const float* __restrict__ fcb,
                        const float* __restrict__ g, const float* __restrict__ b,
                        __nv_bfloat16* __restrict__ hi, __nv_bfloat16* __restrict__ lo)
{
    const int row = blockIdx.x;
    const int tid = threadIdx.x;
    __shared__ float sv[N];

    float s = 0.0f, s2 = 0.0f;
    #pragma unroll
    for (int j = tid; j < N; j += 256) {
        float v = xa[(size_t)row * N + j] + xb[(size_t)row * N + j] + fcb[j];
        sv[j] = v;
        s += v; s2 += v * v;
    }
    __shared__ float rs[256], rs2[256];
    rs[tid] = s; rs2[tid] = s2;
    __syncthreads();
    #pragma unroll
    for (int o = 128; o > 0; o >>= 1) {
        if (tid < o) { rs[tid] += rs[tid + o]; rs2[tid] += rs2[tid + o]; }
        __syncthreads();
    }
    float mu  = rs[0]  * (1.0f / N);
    float var = rs2[0] * (1.0f / N) - mu * mu;
    float inv = rsqrtf(var + 1e-5f);

    #pragma unroll
    for (int j = tid; j < N; j += 256) {
        float v = (sv[j] - mu) * inv * g[j] + b[j];
        float gv = 0.5f * v * (1.0f + erff(v * 0.70710678118654752f));
        __nv_bfloat16 hb = __float2bfloat16(gv);
        hi[(size_t)row * N + j] = hb;
        lo[(size_t)row * N + j] = __float2bfloat16(gv - __bfloat162float(hb));
    }
}

__global__ void softmax_store(const float* __restrict__ za, const float* __restrict__ zb,
                              const float* __restrict__ fcb,
                              __nv_bfloat16* __restrict__ ohi, __nv_bfloat16* __restrict__ olo,
                              float* __restrict__ dst, int t)
{
    const int b = blockIdx.x;
    const int j = threadIdx.x;     // 256 == DDIM
    float v = za[(size_t)b * DDIM + j] + zb[(size_t)b * DDIM + j] + fcb[j];

    __shared__ float red[256];
    red[j] = v;
    __syncthreads();
    #pragma unroll
    for (int o = 128; o > 0; o >>= 1) {
        if (j < o) red[j] = fmaxf(red[j], red[j + o]);
        __syncthreads();
    }
    float m = red[0];
    __syncthreads();
    float e = expf(v - m);
    red[j] = e;
    __syncthreads();
    #pragma unroll
    for (int o = 128; o > 0; o >>= 1) {
        if (j < o) red[j] += red[j + o];
        __syncthreads();
    }
    float p = e / red[0];
    __nv_bfloat16 hb = __float2bfloat16(p);
    ohi[(size_t)b * DDIM + j] = hb;
    olo[(size_t)b * DDIM + j] = __float2bfloat16(p - __bfloat162float(hb));
    dst[((size_t)b * TLEN + t) * DDIM + j] = p;
}

// ===================== mma.sync split-bf16 batched GEMM ======================
// Per-job: C[M, N] = (Ahi+Alo)[M, kOff:kOff+kLen] @ (Bhi+Blo)[N, kOff:kOff+kLen]^T
// (lo*lo dropped).  No bias (consumers add).  blockIdx.z selects the job.
struct Job {
    const __nv_bfloat16 *Ahi, *Alo, *Bhi, *Blo;
    float* C;
    int K, kOff, kLen;
};
struct Jobs4 { Job j[4]; };

template <int BM, int BN, int WM, int WN>
__global__ __launch_bounds__(256)
void gemm_batch(Jobs4 jobs, int N)
{
    constexpr int PITCH = 80;
    constexpr int A_SZ  = BM * PITCH;
    constexpr int B_SZ  = BN * PITCH;
    constexpr int STAGE = 2 * A_SZ + 2 * B_SZ;
    constexpr int WARPS_N = BN / WN;
    constexpr int MT  = WM / 16;
    constexpr int NT  = WN / 8;
    constexpr int NT2 = WN / 16;

    extern __shared__ char smem[];
    const uint32_t sb = smem_u32(smem);
    const int tid  = threadIdx.x;
    const int wid  = tid >> 5;
    const int lane = tid & 31;
    const int wm0 = (wid / WARPS_N) * WM;
    const int wn0 = (wid % WARPS_N) * WN;
    const int row0 = blockIdx.y * BM;
    const int col0 = blockIdx.x * BN;

    const Job jb = jobs.j[blockIdx.z];
    const int K  = jb.K;
    const int NC = jb.kLen >> 5;
    const __nv_bfloat16* __restrict__ Ahi = jb.Ahi;
    const __nv_bfloat16* __restrict__ Alo = jb.Alo;
    const __nv_bfloat16* __restrict__ Bhi = jb.Bhi;
    const __nv_bfloat16* __restrict__ Blo = jb.Blo;

    float acc[MT][NT][4] = {};

    auto copy_chunk = [&](int c, int buf) {
        const uint32_t base = sb + buf * STAGE;
        const int kb = jb.kOff + (c << 5);
        #pragma unroll
        for (int i = tid; i < BM * 4; i += 256) {
            int r = i >> 2, q = i & 3;
            size_t g = (size_t)(row0 + r) * K + kb + q * 8;
            uint32_t d = base + r * PITCH + q * 16;
            cpasync16(d,        Ahi + g);
            cpasync16(d + A_SZ, Alo + g);
        }
        #pragma unroll
        for (int i = tid; i < BN * 4; i += 256) {
            int r = i >> 2, q = i & 3;
            size_t g = (size_t)(col0 + r) * K + kb + q * 8;
            uint32_t d = base + 2 * A_SZ + r * PITCH + q * 16;
            cpasync16(d,        Bhi + g);
            cpasync16(d + B_SZ, Blo + g);
        }
    };

    copy_chunk(0, 0);
    CP_COMMIT;

    int buf = 0;
    for (int c = 0; c < NC; c++) {
        CP_WAIT0;
        __syncthreads();
        if (c + 1 < NC) { copy_chunk(c + 1, buf ^ 1); CP_COMMIT; }

        const uint32_t aBase = sb + buf * STAGE;
        const uint32_t bBase = aBase + 2 * A_SZ;

        #pragma unroll
        for (int ks = 0; ks < 2; ks++) {
            uint32_t ah[MT][4], al[MT][4], bh[NT2][4], bl[NT2][4];
            #pragma unroll
            for (int mt = 0; mt < MT; mt++) {
                uint32_t ad = aBase + (wm0 + mt * 16 + (lane & 15)) * PITCH
                            + ks * 32 + ((lane >> 4) << 4);
                ldmx4(ah[mt], ad);
                ldmx4(al[mt], ad + A_SZ);
            }
            #pragma unroll
            for (int n2 = 0; n2 < NT2; n2++) {
                int nr = wn0 + n2 * 16 + (lane & 7) + ((lane & 16) ? 8 : 0);
                uint32_t bd = bBase + nr * PITCH + ks * 32 + ((lane & 8) ? 16 : 0);
                ldmx4(bh[n2], bd);
                ldmx4(bl[n2], bd + B_SZ);
            }
            #pragma unroll
            for (int mt = 0; mt < MT; mt++)
                #pragma unroll
                for (int nt = 0; nt < NT; nt++) {
                    const uint32_t* bph = &bh[nt >> 1][(nt & 1) * 2];
                    const uint32_t* bpl = &bl[nt >> 1][(nt & 1) * 2];
                    mma_bf16(acc[mt][nt], ah[mt], bph);
                    mma_bf16(acc[mt][nt], ah[mt], bpl);
                    mma_bf16(acc[mt][nt], al[mt], bph);
                }
        }
        __syncthreads();
        buf ^= 1;
    }

    float* __restrict__ C = jb.C;
    #pragma unroll
    for (int mt = 0; mt < MT; mt++) {
        int r0 = row0 + wm0 + mt * 16 + (lane >> 2);
        #pragma unroll
        for (int nt = 0; nt < NT; nt++) {
            int cc = col0 + wn0 + nt * 8 + (lane & 3) * 2;
            float2 v0 = { acc[mt][nt][0], acc[mt][nt][1] };
            float2 v1 = { acc[mt][nt][2], acc[mt][nt][3] };
            *(float2*)(C + (size_t)r0 * N + cc)       = v0;
            *(float2*)(C + (size_t)(r0 + 8) * N + cc) = v1;
        }
    }
}

// ============================ host side ======================================
#define SMEM_BIG   (2 * (2 * 128 * 80 + 2 * 64 * 80))   // 61440
#define SMEM_SMALL (2 * (2 * 64 * 80 + 2 * 64 * 80))    // 40960

extern "C" void kernel_launch(void* const* d_in, const int* in_sizes, int n_in,
                              void* d_out, int out_size)
{
    const float* hidden = (const float*)d_in[0];
    const float* W_ih0  = (const float*)d_in[1];
    const float* W_hh0  = (const float*)d_in[2];
    const float* b_ih0  = (const float*)d_in[3];
    const float* b_hh0  = (const float*)d_in[4];
    const float* W_ih1  = (const float*)d_in[5];
    const float* W_hh1  = (const float*)d_in[6];
    const float* b_ih1  = (const float*)d_in[7];
    const float* b_hh1  = (const float*)d_in[8];
    const float* fc1_w  = (const float*)d_in[9];
    const float* fc1_b  = (const float*)d_in[10];
    const float* ln1_g  = (const float*)d_in[11];
    const float* ln1_b  = (const float*)d_in[12];
    const float* fc2_w  = (const float*)d_in[13];
    const float* fc2_b  = (const float*)d_in[14];
    const float* ln2_g  = (const float*)d_in[15];
    const float* ln2_b  = (const float*)d_in[16];
    const float* fc3_w  = (const float*)d_in[17];
    const float* fc3_b  = (const float*)d_in[18];
    float* out = (float*)d_out;

    cudaFuncSetAttribute((const void*)gemm_batch<128, 64, 32, 32>,
                         cudaFuncAttributeMaxDynamicSharedMemorySize, SMEM_BIG);
    cudaFuncSetAttribute((const void*)gemm_batch<64, 64, 16, 32>,
                         cudaFuncAttributeMaxDynamicSharedMemorySize, SMEM_SMALL);

    float *h0f, *h1f, *giA, *giB, *ghA, *ghB, *z1A, *z1B, *z2A, *z2B, *z3A, *z3B;
    __nv_bfloat16 *ohi, *olo, *h0hi, *h0lo, *h1hi, *h1lo, *z1hi, *z1lo, *z2hi, *z2lo;
    __nv_bfloat16 *wih0h, *wih0l, *whh0h, *whh0l, *wih1h, *wih1l, *whh1h, *whh1l;
    __nv_bfloat16 *f1h, *f1l, *f2h, *f2l, *f3h, *f3l;
    cudaGetSymbolAddress((void**)&h0f, g_h0f);  cudaGetSymbolAddress((void**)&h1f, g_h1f);
    cudaGetSymbolAddress((void**)&giA, g_giA);  cudaGetSymbolAddress((void**)&giB, g_giB);
    cudaGetSymbolAddress((void**)&ghA, g_ghA);  cudaGetSymbolAddress((void**)&ghB, g_ghB);
    cudaGetSymbolAddress((void**)&z1A, g_z1A);  cudaGetSymbolAddress((void**)&z1B, g_z1B);
    cudaGetSymbolAddress((void**)&z2A, g_z2A);  cudaGetSymbolAddress((void**)&z2B, g_z2B);
    cudaGetSymbolAddress((void**)&z3A, g_z3A);  cudaGetSymbolAddress((void**)&z3B, g_z3B);
    cudaGetSymbolAddress((void**)&ohi, g_out_hi); cudaGetSymbolAddress((void**)&olo, g_out_lo);
    cudaGetSymbolAddress((void**)&h0hi, g_h0_hi); cudaGetSymbolAddress((void**)&h0lo, g_h0_lo);
    cudaGetSymbolAddress((void**)&h1hi, g_h1_hi); cudaGetSymbolAddress((void**)&h1lo, g_h1_lo);
    cudaGetSymbolAddress((void**)&z1hi, g_z1_hi); cudaGetSymbolAddress((void**)&z1lo, g_z1_lo);
    cudaGetSymbolAddress((void**)&z2hi, g_z2_hi); cudaGetSymbolAddress((void**)&z2lo, g_z2_lo);
    cudaGetSymbolAddress((void**)&wih0h, g_wih0_hi); cudaGetSymbolAddress((void**)&wih0l, g_wih0_lo);
    cudaGetSymbolAddress((void**)&whh0h, g_whh0_hi); cudaGetSymbolAddress((void**)&whh0l, g_whh0_lo);
    cudaGetSymbolAddress((void**)&wih1h, g_wih1_hi); cudaGetSymbolAddress((void**)&wih1l, g_wih1_lo);
    cudaGetSymbolAddress((void**)&whh1h, g_whh1_hi); cudaGetSymbolAddress((void**)&whh1l, g_whh1_lo);
    cudaGetSymbolAddress((void**)&f1h, g_fc1_hi); cudaGetSymbolAddress((void**)&f1l, g_fc1_lo);
    cudaGetSymbolAddress((void**)&f2h, g_fc2_hi); cudaGetSymbolAddress((void**)&f2l, g_fc2_lo);
    cudaGetSymbolAddress((void**)&f3h, g_fc3_hi); cudaGetSymbolAddress((void**)&f3l, g_fc3_lo);

    auto split = [](const float* src, __nv_bfloat16* hi, __nv_bfloat16* lo, int n) {
        split_kernel<<<n / 256, 256>>>(src, hi, lo, n);
    };
    split(W_ih0, wih0h, wih0l, 3 * HDIM * DDIM);
    split(W_hh0, whh0h, whh0l, 3 * HDIM * HDIM);
    split(W_ih1, wih1h, wih1l, 3 * HDIM * HDIM);
    split(W_hh1, whh1h, whh1l, 3 * HDIM * HDIM);
    split(fc1_w, f1h, f1l, FC1N * HDIM);
    split(fc2_w, f2h, f2l, FC2N * FC1N);
    split(fc3_w, f3h, f3l, DDIM * FC2N);

    init_kernel<<<(BSZ * HDIM + 255) / 256, 256>>>(hidden);

    for (int t = 0; t < TLEN; t++) {
        // ---- GRU layer 0: 4 sub-jobs in one launch (384 CTAs) ----
        {
            Jobs4 J;
            J.j[0] = { ohi,  olo,  wih0h, wih0l, giA, DDIM, 0,   128 };
            J.j[1] = { ohi,  olo,  wih0h, wih0l, giB, DDIM, 128, 128 };
            J.j[2] = { h0hi, h0lo, whh0h, whh0l, ghA, HDIM, 0,   512 };
            J.j[3] = { h0hi, h0lo, whh0h, whh0l, ghB, HDIM, 512, 512 };
            dim3 grid(3 * HDIM / 64, BSZ / 128, 4);
            gemm_batch<128, 64, 32, 32><<<grid, 256, SMEM_BIG>>>(J, 3 * HDIM);
        }
        gru_gate<<<(BSZ * HDIM / 4) / 256, 256>>>(
            (const float4*)giA, (const float4*)giB, (const float4*)ghA, (const float4*)ghB,
            (const float4*)b_ih0, (const float4*)b_hh0, (float4*)h0f, h0hi, h0lo);

        // ---- GRU layer 1: 4 sub-jobs in one launch (384 CTAs) ----
        {
            Jobs4 J;
            J.j[0] = { h0hi, h0lo, wih1h, wih1l, giA, HDIM, 0,   512 };
            J.j[1] = { h0hi, h0lo, wih1h, wih1l, giB, HDIM, 512, 512 };
            J.j[2] = { h1hi, h1lo, whh1h, whh1l, ghA, HDIM, 0,   512 };
            J.j[3] = { h1hi, h1lo, whh1h, whh1l, ghB, HDIM, 512, 512 };
            dim3 grid(3 * HDIM / 64, BSZ / 128, 4);
            gemm_batch<128, 64, 32, 32><<<grid, 256, SMEM_BIG>>>(J, 3 * HDIM);
        }
        gru_gate<<<(BSZ * HDIM / 4) / 256, 256>>>(
            (const float4*)giA, (const float4*)giB, (const float4*)ghA, (const float4*)ghB,
            (const float4*)b_ih1, (const float4*)b_hh1, (float4*)h1f, h1hi, h1lo);

        // ---- FC head (split-K=2, BM=64 tiles) ----
        {
            Jobs4 J;
            J.j[0] = { h1hi, h1lo, f1h, f1l, z1A, HDIM, 0,   512 };
            J.j[1] = { h1hi, h1lo, f1h, f1l, z1B, HDIM, 512, 512 };
            dim3 grid(FC1N / 64, BSZ / 64, 2);
            gemm_batch<64, 64, 16, 32><<<grid, 256, SMEM_SMALL>>>(J, FC1N);
        }
        ln_gelu<FC1N><<<BSZ, 256>>>(z1A, z1B, fc1_b, ln1_g, ln1_b, z1hi, z1lo);
        {
            Jobs4 J;
            J.j[0] = { z1hi, z1lo, f2h, f2l, z2A, FC1N, 0,   512 };
            J.j[1] = { z1hi, z1lo, f2h, f2l, z2B, FC1N, 512, 512 };
            dim3 grid(FC2N / 64, BSZ / 64, 2);
            gemm_batch<64, 64, 16, 32><<<grid, 256, SMEM_SMALL>>>(J, FC2N);
        }
        ln_gelu<FC2N><<<BSZ, 256>>>(z2A, z2B, fc2_b, ln2_g, ln2_b, z2hi, z2lo);
        {
            Jobs4 J;
            J.j[0] = { z2hi, z2lo, f3h, f3l, z3A, FC2N, 0,   256 };
            J.j[1] = { z2hi, z2lo, f3h, f3l, z3B, FC2N, 256, 256 };
            dim3 grid(DDIM / 64, BSZ / 64, 2);
            gemm_batch<64, 64, 16, 32><<<grid, 256, SMEM_SMALL>>>(J, DDIM);
        }
        softmax_store<<<BSZ, DDIM>>>(z3A, z3B, fc3_b, ohi, olo, out, t);
    }
}